// round 3
// baseline (speedup 1.0000x reference)
#include <cuda_runtime.h>
#include <cstdint>
#include <cstddef>

// FixedGraphAttentionLayer: bs=4, L=20000, D=16, Fin=Fout=128
// Rewrite: y = x @ W per node (80K rows) instead of per (node,neighbor) (1.28M rows).
//   h[b,l,d,:] == y[b, adj[b,l,d], :]   (matmul is linear; exact)
//   e[b,l,d]   == s1[b,adj[b,l,d]] + s2[b,adj[b,l,0]],  s1=y@a1, s2=y@a2
// adj dtype (int32 vs int64) is detected at runtime: JAX without x64 silently
// downcasts jnp.int64 -> int32, and in_sizes can't distinguish them.

#define LRELU_ALPHA 0.2f
static constexpr int BS = 4;
static constexpr int L  = 20000;
static constexpr int D  = 16;
static constexpr int F  = 128;
static constexpr int NROWS = BS * L;        // 80000
static constexpr int ROWS_PER_BLK = 64;     // kernel 1 tile
static constexpr int K1_THREADS = 256;

// Scratch (no cudaMalloc allowed): 41 MB y + scores + dtype flag
__device__ __align__(16) float g_y[(size_t)NROWS * F];
__device__ float g_s1[NROWS];
__device__ float g_s2[NROWS];
__device__ int   g_adj_is64;

// ---------------------------------------------------------------------------
// Prepass: detect whether adj is int64 (odd 32-bit words all zero, since
// values < 20000 < 2^31) or int32. Reads only 256 bytes — safe either way.
// ---------------------------------------------------------------------------
__global__ void detect_adj_kernel(const int* __restrict__ adj32)
{
    int is64 = 1;
    #pragma unroll
    for (int k = 0; k < 32; k++)
        if (adj32[2 * k + 1] != 0) is64 = 0;
    g_adj_is64 = is64;
}

// ---------------------------------------------------------------------------
// Kernel 1: y = x @ W  (rows x 128 @ 128 x 128), plus s1 = y.a1, s2 = y.a2
// Block: 256 threads, 64 rows. Thread (tx,ty): cols 4*tx..4*tx+3, rows ty*8..ty*8+7.
// X tile in static smem (32 KB); W streamed from L1 (64 KB, fully resident).
// Packed f32x2 FMA (3-reg FFMA is half-rate on sm_103a).
// ---------------------------------------------------------------------------
__global__ __launch_bounds__(K1_THREADS, 2)
void gemm_scores_kernel(const float* __restrict__ x,
                        const float* __restrict__ W,
                        const float* __restrict__ a)
{
    __shared__ float Xsm[ROWS_PER_BLK * F];   // 32 KB

    const int tid = threadIdx.x;
    const int tx  = tid & 31;        // col group (4 cols each)
    const int ty  = tid >> 5;        // row group (8 rows each)
    const int rowbase = blockIdx.x * ROWS_PER_BLK;

    // Cooperative X load (float4, coalesced)
    {
        const float4* Xg  = (const float4*)(x + (size_t)rowbase * F);
        float4*       Xs4 = (float4*)Xsm;
        #pragma unroll
        for (int i = tid; i < ROWS_PER_BLK * F / 4; i += K1_THREADS) Xs4[i] = Xg[i];
    }
    __syncthreads();

    unsigned long long acc01[8], acc23[8];
    #pragma unroll
    for (int r = 0; r < 8; r++) { acc01[r] = 0ull; acc23[r] = 0ull; }

    const float4* Wg = (const float4*)W;      // row-major [128][128], float4 view: k*32 + tx
    #pragma unroll 4
    for (int k = 0; k < F; k++) {
        float4 w = Wg[k * 32 + tx];           // warp loads 512B contiguous, L1-hot
        unsigned long long w01, w23;
        asm("mov.b64 %0, {%1,%2};" : "=l"(w01) : "f"(w.x), "f"(w.y));
        asm("mov.b64 %0, {%1,%2};" : "=l"(w23) : "f"(w.z), "f"(w.w));
        #pragma unroll
        for (int r = 0; r < 8; r++) {
            float xv = Xsm[(ty * 8 + r) * F + k];         // warp-broadcast LDS
            unsigned long long xx;
            asm("mov.b64 %0, {%1,%1};" : "=l"(xx) : "f"(xv));
            asm("fma.rn.f32x2 %0, %1, %2, %0;" : "+l"(acc01[r]) : "l"(xx), "l"(w01));
            asm("fma.rn.f32x2 %0, %1, %2, %0;" : "+l"(acc23[r]) : "l"(xx), "l"(w23));
        }
    }

    // attention vectors for this thread's 4 columns
    const float a10 = a[4 * tx + 0], a11 = a[4 * tx + 1];
    const float a12 = a[4 * tx + 2], a13 = a[4 * tx + 3];
    const float a20 = a[F + 4 * tx + 0], a21 = a[F + 4 * tx + 1];
    const float a22 = a[F + 4 * tx + 2], a23 = a[F + 4 * tx + 3];

    #pragma unroll
    for (int r = 0; r < 8; r++) {
        float v0, v1, v2, v3;
        asm("mov.b64 {%0,%1}, %2;" : "=f"(v0), "=f"(v1) : "l"(acc01[r]));
        asm("mov.b64 {%0,%1}, %2;" : "=f"(v2), "=f"(v3) : "l"(acc23[r]));
        const int row = rowbase + ty * 8 + r;
        *(float4*)(g_y + (size_t)row * F + 4 * tx) = make_float4(v0, v1, v2, v3);

        float p1 = v0 * a10 + v1 * a11 + v2 * a12 + v3 * a13;
        float p2 = v0 * a20 + v1 * a21 + v2 * a22 + v3 * a23;
        #pragma unroll
        for (int o = 16; o > 0; o >>= 1) {
            p1 += __shfl_xor_sync(0xffffffffu, p1, o);
            p2 += __shfl_xor_sync(0xffffffffu, p2, o);
        }
        if (tx == 0) { g_s1[row] = p1; g_s2[row] = p2; }
    }
}

// ---------------------------------------------------------------------------
// Kernel 2: one warp per node. Softmax(leaky_relu(e)) over D=16, then
// out[f] = elu( sum_d attn_d * y[b, adj_d, f] ). Each lane owns 4 f-values.
// ---------------------------------------------------------------------------
__global__ __launch_bounds__(256)
void attn_out_kernel(const int* __restrict__ adj32,
                     float* __restrict__ out)
{
    const int warp = (blockIdx.x * blockDim.x + threadIdx.x) >> 5;
    const int lane = threadIdx.x & 31;
    if (warp >= NROWS) return;

    const int b = warp / L;
    const size_t nodebase = (size_t)b * L;
    const int is64 = g_adj_is64;

    int   idx = 0;
    float e   = -INFINITY;
    if (lane < D) {
        const size_t ei = (size_t)warp * D + lane;
        int raw = is64 ? adj32[2 * ei] : adj32[ei];   // int64: little-endian low word
        raw = raw < 0 ? 0 : (raw >= L ? L - 1 : raw); // defensive clamp (no-op if data valid)
        idx = raw;
        e   = g_s1[nodebase + idx];
    }
    const int idx0 = __shfl_sync(0xffffffffu, idx, 0);
    const float s2v = g_s2[nodebase + idx0];
    if (lane < D) {
        e += s2v;
        e = (e >= 0.f) ? e : LRELU_ALPHA * e;   // leaky_relu before softmax
    }

    // softmax over the 16 valid lanes (invalid lanes hold -inf -> exp = 0)
    float m = e;
    #pragma unroll
    for (int o = 16; o > 0; o >>= 1) m = fmaxf(m, __shfl_xor_sync(0xffffffffu, m, o));
    float p = (lane < D) ? __expf(e - m) : 0.f;
    float s = p;
    #pragma unroll
    for (int o = 16; o > 0; o >>= 1) s += __shfl_xor_sync(0xffffffffu, s, o);
    const float attn = p / s;

    // weighted gather of 16 y-rows (512 B each, coalesced across the warp)
    const float* yb = g_y + nodebase * F;
    float4 acc = make_float4(0.f, 0.f, 0.f, 0.f);
    #pragma unroll
    for (int d = 0; d < D; d++) {
        const int   id = __shfl_sync(0xffffffffu, idx,  d);
        const float w  = __shfl_sync(0xffffffffu, attn, d);
        float4 v = *(const float4*)(yb + (size_t)id * F + 4 * lane);
        acc.x += w * v.x; acc.y += w * v.y; acc.z += w * v.z; acc.w += w * v.w;
    }

    // elu (alpha = 1)
    acc.x = acc.x > 0.f ? acc.x : expm1f(acc.x);
    acc.y = acc.y > 0.f ? acc.y : expm1f(acc.y);
    acc.z = acc.z > 0.f ? acc.z : expm1f(acc.z);
    acc.w = acc.w > 0.f ? acc.w : expm1f(acc.w);

    *(float4*)(out + (size_t)warp * F + 4 * lane) = acc;
}

// ---------------------------------------------------------------------------
extern "C" void kernel_launch(void* const* d_in, const int* in_sizes, int n_in,
                              void* d_out, int out_size)
{
    // Identify inputs by element count (robust to ordering):
    //   x: 10,240,000 f32 | adj: 1,280,000 (i32 or i64) | W: 16,384 f32 | a: 256 f32
    const float* x   = nullptr;
    const int*   adj = nullptr;
    const float* W   = nullptr;
    const float* a   = nullptr;
    for (int i = 0; i < n_in; i++) {
        switch (in_sizes[i]) {
            case NROWS * F: x   = (const float*)d_in[i]; break;
            case NROWS * D: adj = (const int*)d_in[i];   break;
            case F * F:     W   = (const float*)d_in[i]; break;
            case 2 * F:     a   = (const float*)d_in[i]; break;
            default: break;
        }
    }
    float* out = (float*)d_out;

    detect_adj_kernel<<<1, 1>>>(adj);
    gemm_scores_kernel<<<NROWS / ROWS_PER_BLK, K1_THREADS>>>(x, W, a);
    attn_out_kernel<<<(NROWS * 32) / 256, 256>>>(adj, out);
}

// round 4
// speedup vs baseline: 1.0931x; 1.0931x over previous
#include <cuda_runtime.h>
#include <cuda_fp16.h>
#include <cstdint>
#include <cstddef>

// FixedGraphAttentionLayer: bs=4, L=20000, D=16, Fin=Fout=128
// Rewrite: y = x @ W per node (80K rows) instead of per (node,neighbor) (1.28M rows).
//   h[b,l,d,:] == y[b, adj[b,l,d], :]   (matmul is linear; exact)
//   e[b,l,d]   == s1[b,adj[b,l,d]] + s2[b,adj[b,l,0]],  s1=y@a1, s2=y@a2
// y stored as fp16 (scores stay fp32) to halve kernel-2 L2 gather traffic.
// adj dtype (int32 vs int64) detected at runtime (JAX w/o x64 downcasts to i32).

#define LRELU_ALPHA 0.2f
static constexpr int BS = 4;
static constexpr int L  = 20000;
static constexpr int D  = 16;
static constexpr int F  = 128;
static constexpr int NROWS = BS * L;        // 80000
static constexpr int ROWS_PER_BLK = 64;     // kernel 1 tile
static constexpr int K1_THREADS = 256;

// Scratch (no cudaMalloc allowed): 20.5 MB y(fp16) + scores + dtype flag
__device__ __align__(16) __half g_yh[(size_t)NROWS * F];
__device__ float g_s1[NROWS];
__device__ float g_s2[NROWS];
__device__ int   g_adj_is64;

// ---------------------------------------------------------------------------
// Prepass (1 warp): adj is int64 iff odd 32-bit words are all zero (values
// < 20000 < 2^31). Checks 64 words (512 B, safe for both dtypes).
// False-positive prob ~ (5e-5)^64 ~ 0.
// ---------------------------------------------------------------------------
__global__ void detect_adj_kernel(const int* __restrict__ adj32)
{
    const int t = threadIdx.x;
    const int bad = (adj32[2 * t + 1] != 0) | (adj32[2 * t + 65] != 0);
    const unsigned m = __ballot_sync(0xffffffffu, bad);
    if (t == 0) g_adj_is64 = (m == 0u);
}

// ---------------------------------------------------------------------------
// Kernel 1: y = x @ W  (rows x 128 @ 128 x 128), plus s1 = y.a1, s2 = y.a2
// Block: 256 threads, 64 rows. Thread (tx,ty): cols 4*tx..4*tx+3, rows ty*8..ty*8+7.
// X tile in static smem (32 KB); W streamed from L1 (64 KB, fully resident).
// Packed f32x2 FMA (3-reg FFMA is half-rate on sm_103a).
// ---------------------------------------------------------------------------
__global__ __launch_bounds__(K1_THREADS, 2)
void gemm_scores_kernel(const float* __restrict__ x,
                        const float* __restrict__ W,
                        const float* __restrict__ a)
{
    __shared__ float Xsm[ROWS_PER_BLK * F];   // 32 KB

    const int tid = threadIdx.x;
    const int tx  = tid & 31;        // col group (4 cols each)
    const int ty  = tid >> 5;        // row group (8 rows each)
    const int rowbase = blockIdx.x * ROWS_PER_BLK;

    // Cooperative X load (float4, coalesced)
    {
        const float4* Xg  = (const float4*)(x + (size_t)rowbase * F);
        float4*       Xs4 = (float4*)Xsm;
        #pragma unroll
        for (int i = tid; i < ROWS_PER_BLK * F / 4; i += K1_THREADS) Xs4[i] = Xg[i];
    }
    __syncthreads();

    unsigned long long acc01[8], acc23[8];
    #pragma unroll
    for (int r = 0; r < 8; r++) { acc01[r] = 0ull; acc23[r] = 0ull; }

    const float4* Wg = (const float4*)W;      // row-major [128][128], float4 view: k*32 + tx
    #pragma unroll 4
    for (int k = 0; k < F; k++) {
        float4 w = Wg[k * 32 + tx];           // warp loads 512B contiguous, L1-hot
        unsigned long long w01, w23;
        asm("mov.b64 %0, {%1,%2};" : "=l"(w01) : "f"(w.x), "f"(w.y));
        asm("mov.b64 %0, {%1,%2};" : "=l"(w23) : "f"(w.z), "f"(w.w));
        #pragma unroll
        for (int r = 0; r < 8; r++) {
            float xv = Xsm[(ty * 8 + r) * F + k];         // warp-broadcast LDS
            unsigned long long xx;
            asm("mov.b64 %0, {%1,%1};" : "=l"(xx) : "f"(xv));
            asm("fma.rn.f32x2 %0, %1, %2, %0;" : "+l"(acc01[r]) : "l"(xx), "l"(w01));
            asm("fma.rn.f32x2 %0, %1, %2, %0;" : "+l"(acc23[r]) : "l"(xx), "l"(w23));
        }
    }

    // attention vectors for this thread's 4 columns
    const float a10 = a[4 * tx + 0], a11 = a[4 * tx + 1];
    const float a12 = a[4 * tx + 2], a13 = a[4 * tx + 3];
    const float a20 = a[F + 4 * tx + 0], a21 = a[F + 4 * tx + 1];
    const float a22 = a[F + 4 * tx + 2], a23 = a[F + 4 * tx + 3];

    #pragma unroll
    for (int r = 0; r < 8; r++) {
        float v0, v1, v2, v3;
        asm("mov.b64 {%0,%1}, %2;" : "=f"(v0), "=f"(v1) : "l"(acc01[r]));
        asm("mov.b64 {%0,%1}, %2;" : "=f"(v2), "=f"(v3) : "l"(acc23[r]));
        const int row = rowbase + ty * 8 + r;

        // store y as fp16 (8 B per thread per row)
        __half2 h01 = __floats2half2_rn(v0, v1);
        __half2 h23 = __floats2half2_rn(v2, v3);
        uint2 st;
        st.x = *reinterpret_cast<unsigned*>(&h01);
        st.y = *reinterpret_cast<unsigned*>(&h23);
        *(uint2*)(g_yh + (size_t)row * F + 4 * tx) = st;

        // scores from full-precision accumulators
        float p1 = v0 * a10 + v1 * a11 + v2 * a12 + v3 * a13;
        float p2 = v0 * a20 + v1 * a21 + v2 * a22 + v3 * a23;
        #pragma unroll
        for (int o = 16; o > 0; o >>= 1) {
            p1 += __shfl_xor_sync(0xffffffffu, p1, o);
            p2 += __shfl_xor_sync(0xffffffffu, p2, o);
        }
        if (tx == 0) { g_s1[row] = p1; g_s2[row] = p2; }
    }
}

// ---------------------------------------------------------------------------
// Kernel 2: one warp per node. Softmax(leaky_relu(e)) over D=16, then
// out[f] = elu( sum_d attn_d * y[b, adj_d, f] ). Each lane owns 4 f-values.
// y gathered as fp16 (256 B/row), accumulated in fp32.
// ---------------------------------------------------------------------------
__global__ __launch_bounds__(256)
void attn_out_kernel(const int* __restrict__ adj32,
                     float* __restrict__ out)
{
    const int warp = (blockIdx.x * blockDim.x + threadIdx.x) >> 5;
    const int lane = threadIdx.x & 31;
    if (warp >= NROWS) return;

    const int b = warp / L;
    const size_t nodebase = (size_t)b * L;
    const int is64 = g_adj_is64;

    int   idx = 0;
    float e   = -INFINITY;
    if (lane < D) {
        const size_t ei = (size_t)warp * D + lane;
        int raw = is64 ? adj32[2 * ei] : adj32[ei];   // int64: little-endian low word
        raw = raw < 0 ? 0 : (raw >= L ? L - 1 : raw); // defensive clamp (no-op if data valid)
        idx = raw;
        e   = g_s1[nodebase + idx];
    }
    const int idx0 = __shfl_sync(0xffffffffu, idx, 0);
    const float s2v = g_s2[nodebase + idx0];
    if (lane < D) {
        e += s2v;
        e = (e >= 0.f) ? e : LRELU_ALPHA * e;   // leaky_relu before softmax
    }

    // softmax over the 16 valid lanes (invalid lanes hold -inf -> exp = 0)
    float m = e;
    #pragma unroll
    for (int o = 16; o > 0; o >>= 1) m = fmaxf(m, __shfl_xor_sync(0xffffffffu, m, o));
    float p = (lane < D) ? __expf(e - m) : 0.f;
    float s = p;
    #pragma unroll
    for (int o = 16; o > 0; o >>= 1) s += __shfl_xor_sync(0xffffffffu, s, o);
    const float attn = p / s;

    // weighted gather of 16 y-rows (256 B each, coalesced across the warp)
    const __half* yb = g_yh + nodebase * F;
    float4 acc = make_float4(0.f, 0.f, 0.f, 0.f);
    #pragma unroll
    for (int d = 0; d < D; d++) {
        const int   id = __shfl_sync(0xffffffffu, idx,  d);
        const float w  = __shfl_sync(0xffffffffu, attn, d);
        uint2 raw = *(const uint2*)(yb + (size_t)id * F + 4 * lane);
        __half2 h01 = *reinterpret_cast<__half2*>(&raw.x);
        __half2 h23 = *reinterpret_cast<__half2*>(&raw.y);
        float2 f01 = __half22float2(h01);
        float2 f23 = __half22float2(h23);
        acc.x += w * f01.x; acc.y += w * f01.y;
        acc.z += w * f23.x; acc.w += w * f23.y;
    }

    // elu (alpha = 1)
    acc.x = acc.x > 0.f ? acc.x : expm1f(acc.x);
    acc.y = acc.y > 0.f ? acc.y : expm1f(acc.y);
    acc.z = acc.z > 0.f ? acc.z : expm1f(acc.z);
    acc.w = acc.w > 0.f ? acc.w : expm1f(acc.w);

    *(float4*)(out + (size_t)warp * F + 4 * lane) = acc;
}

// ---------------------------------------------------------------------------
extern "C" void kernel_launch(void* const* d_in, const int* in_sizes, int n_in,
                              void* d_out, int out_size)
{
    // Identify inputs by element count (robust to ordering):
    //   x: 10,240,000 f32 | adj: 1,280,000 (i32 or i64) | W: 16,384 f32 | a: 256 f32
    const float* x   = nullptr;
    const int*   adj = nullptr;
    const float* W   = nullptr;
    const float* a   = nullptr;
    for (int i = 0; i < n_in; i++) {
        switch (in_sizes[i]) {
            case NROWS * F: x   = (const float*)d_in[i]; break;
            case NROWS * D: adj = (const int*)d_in[i];   break;
            case F * F:     W   = (const float*)d_in[i]; break;
            case 2 * F:     a   = (const float*)d_in[i]; break;
            default: break;
        }
    }
    float* out = (float*)d_out;

    detect_adj_kernel<<<1, 32>>>(adj);
    gemm_scores_kernel<<<NROWS / ROWS_PER_BLK, K1_THREADS>>>(x, W, a);
    attn_out_kernel<<<(NROWS * 32) / 256, 256>>>(adj, out);
}

// round 5
// speedup vs baseline: 1.5789x; 1.4444x over previous
#include <cuda_runtime.h>
#include <cuda_fp16.h>
#include <cstdint>
#include <cstddef>

// FixedGraphAttentionLayer: bs=4, L=20000, D=16, Fin=Fout=128
//   y = x @ W per node (linear rewrite), y stored fp16.
//   e[b,l,d] = s1[adj[b,l,d]] + s2[adj[b,l,0]]  (scores from fp32 accumulators)
// k1 = HMMA (mma.sync m16n8k16 f16f16f32) GEMM + fused scores.
// prep = adj dtype detect + W fragment pre-pack.

#define LRELU_ALPHA 0.2f
static constexpr int BS = 4;
static constexpr int L  = 20000;
static constexpr int D  = 16;
static constexpr int F  = 128;
static constexpr int NROWS = BS * L;   // 80000

__device__ __align__(16) __half g_yh[(size_t)NROWS * F];   // 20.5 MB
__device__ float g_s1[NROWS];
__device__ float g_s2[NROWS];
__device__ int   g_adj_is64;
__device__ __align__(16) uint2 g_Bpack[8 * 16 * 32];       // [kc][nt][lane], 32 KB

// ---------------------------------------------------------------------------
// Prep: adj dtype detect (int64 iff odd 32-bit words all zero; values < 2^31)
// + pack W (fp32 [k=128][n=128]) into mma.m16n8k16 B fragments (fp16).
//   b0 = {W[k0][n], W[k0+1][n]}, b1 = {W[k0+8][n], W[k0+9][n]},
//   k0 = 16*kc + tg*2, n = 8*nt + g   (g = lane>>2, tg = lane&3)
// ---------------------------------------------------------------------------
__global__ void prep_kernel(const int* __restrict__ adj32,
                            const float* __restrict__ W)
{
    const int t = threadIdx.x;
    if (t < 32) {
        const int bad = (adj32[2 * t + 1] != 0) | (adj32[2 * t + 65] != 0);
        const unsigned m = __ballot_sync(0xffffffffu, bad);
        if (t == 0) g_adj_is64 = (m == 0u);
    }
    for (int e = t; e < 4096; e += 256) {
        const int kc = e >> 9, nt = (e >> 5) & 15, lane = e & 31;
        const int g = lane >> 2, tg = lane & 3;
        const int n = nt * 8 + g, k0 = kc * 16 + tg * 2;
        __half2 b0 = __floats2half2_rn(W[k0 * F + n],      W[(k0 + 1) * F + n]);
        __half2 b1 = __floats2half2_rn(W[(k0 + 8) * F + n], W[(k0 + 9) * F + n]);
        uint2 u;
        u.x = *reinterpret_cast<unsigned*>(&b0);
        u.y = *reinterpret_cast<unsigned*>(&b1);
        g_Bpack[e] = u;
    }
}

// ---------------------------------------------------------------------------
// Kernel 1: y = x @ W via HMMA + fused scores. 128 threads, 64 rows/block.
// Warp w owns rows w*16..w*16+15, all 128 cols (16 n-tiles x 8 k-chunks).
// x tile staged fp16 in smem with XOR swizzle (bank-conflict-free frag loads).
// ---------------------------------------------------------------------------
__global__ __launch_bounds__(128)
void gemm_scores_kernel(const float* __restrict__ x,
                        const float* __restrict__ a)
{
    __shared__ __half2 Xs[64 * 64];   // 16 KB: [row][kh2], kh2 swizzled ^(row&7)*4
    __shared__ uint2   Bs[4096];      // 32 KB: [kc][nt][lane]

    const int tid  = threadIdx.x;
    const int lane = tid & 31;
    const int w    = tid >> 5;
    const int g    = lane >> 2;       // 0..7
    const int tg   = lane & 3;        // 0..3
    const int rowbase = blockIdx.x * 64;

    // copy B fragments (32 KB) global -> smem, coalesced
    {
        const uint4* src = (const uint4*)g_Bpack;
        uint4*       dst = (uint4*)Bs;
        #pragma unroll
        for (int i = tid; i < 2048; i += 128) dst[i] = src[i];
    }
    // load x tile (64x128 fp32) -> fp16 swizzled smem
    #pragma unroll
    for (int j = tid; j < 4096; j += 128) {
        const int r = j >> 6, kh2 = j & 63;
        float2 v = *(const float2*)(x + (size_t)(rowbase + r) * F + kh2 * 2);
        Xs[r * 64 + (kh2 ^ ((r & 7) * 4))] = __floats2half2_rn(v.x, v.y);
    }
    __syncthreads();

    // A fragments for this warp's 16 rows, all 8 k-chunks (32 regs)
    unsigned Areg[8][4];
    {
        const int r0 = w * 16 + g, r1 = r0 + 8;
        const int s  = g * 4;
        #pragma unroll
        for (int kc = 0; kc < 8; kc++) {
            const int kl = kc * 8 + tg, kh = kl + 4;
            Areg[kc][0] = *reinterpret_cast<unsigned*>(&Xs[r0 * 64 + (kl ^ s)]);
            Areg[kc][1] = *reinterpret_cast<unsigned*>(&Xs[r1 * 64 + (kl ^ s)]);
            Areg[kc][2] = *reinterpret_cast<unsigned*>(&Xs[r0 * 64 + (kh ^ s)]);
            Areg[kc][3] = *reinterpret_cast<unsigned*>(&Xs[r1 * 64 + (kh ^ s)]);
        }
    }

    float acc[16][4];
    #pragma unroll
    for (int nt = 0; nt < 16; nt++)
        #pragma unroll
        for (int q = 0; q < 4; q++) acc[nt][q] = 0.f;

    #pragma unroll
    for (int nt = 0; nt < 16; nt++) {
        #pragma unroll
        for (int kc = 0; kc < 8; kc++) {
            const uint2 b = Bs[kc * 512 + nt * 32 + lane];
            asm volatile(
                "mma.sync.aligned.m16n8k16.row.col.f32.f16.f16.f32 "
                "{%0,%1,%2,%3}, {%4,%5,%6,%7}, {%8,%9}, {%0,%1,%2,%3};"
                : "+f"(acc[nt][0]), "+f"(acc[nt][1]), "+f"(acc[nt][2]), "+f"(acc[nt][3])
                : "r"(Areg[kc][0]), "r"(Areg[kc][1]), "r"(Areg[kc][2]), "r"(Areg[kc][3]),
                  "r"(b.x), "r"(b.y));
        }
    }

    // scores from fp32 accumulators: rows g (p1a/p2a) and g+8 (p1b/p2b)
    float p1a = 0.f, p1b = 0.f, p2a = 0.f, p2b = 0.f;
    #pragma unroll
    for (int nt = 0; nt < 16; nt++) {
        const float2 a1p = *(const float2*)(a + nt * 8 + tg * 2);
        const float2 a2p = *(const float2*)(a + F + nt * 8 + tg * 2);
        p1a += acc[nt][0] * a1p.x + acc[nt][1] * a1p.y;
        p1b += acc[nt][2] * a1p.x + acc[nt][3] * a1p.y;
        p2a += acc[nt][0] * a2p.x + acc[nt][1] * a2p.y;
        p2b += acc[nt][2] * a2p.x + acc[nt][3] * a2p.y;
    }
    #pragma unroll
    for (int o = 1; o <= 2; o <<= 1) {   // reduce over tg quad (lanes g*4..g*4+3)
        p1a += __shfl_xor_sync(0xffffffffu, p1a, o);
        p1b += __shfl_xor_sync(0xffffffffu, p1b, o);
        p2a += __shfl_xor_sync(0xffffffffu, p2a, o);
        p2b += __shfl_xor_sync(0xffffffffu, p2b, o);
    }
    if (tg == 0) {
        const int r = rowbase + w * 16 + g;
        g_s1[r] = p1a;  g_s2[r] = p2a;
        g_s1[r + 8] = p1b;  g_s2[r + 8] = p2b;
    }

    // stage y (fp16) back into Xs with the same swizzle, then coalesced store
    __syncthreads();
    {
        const int r0 = w * 16 + g;
        const int s  = g * 4;
        #pragma unroll
        for (int nt = 0; nt < 16; nt++) {
            const int c = nt * 4 + tg;
            Xs[r0 * 64 + (c ^ s)]       = __floats2half2_rn(acc[nt][0], acc[nt][1]);
            Xs[(r0 + 8) * 64 + (c ^ s)] = __floats2half2_rn(acc[nt][2], acc[nt][3]);
        }
    }
    __syncthreads();
    {
        const int r = tid >> 1;                 // 2 threads per row
        const int s = (r & 7) * 4;
        const int base = (tid & 1) * 32;        // half2 offset
        __half* dst = g_yh + (size_t)(rowbase + r) * F + base * 2;
        #pragma unroll
        for (int j = 0; j < 8; j++) {
            // (base+j*4) and s both multiples of 4 -> 16B chunk stays contiguous
            uint4 v = *reinterpret_cast<uint4*>(&Xs[r * 64 + ((base + j * 4) ^ s)]);
            *reinterpret_cast<uint4*>(dst + j * 8) = v;
        }
    }
}

// ---------------------------------------------------------------------------
// Kernel 2: one warp per node. softmax(leaky_relu(e)) over D=16, weighted
// fp16 gather (fp32 accumulate), elu. Each lane owns 4 output cols.
// ---------------------------------------------------------------------------
__global__ __launch_bounds__(256)
void attn_out_kernel(const int* __restrict__ adj32,
                     float* __restrict__ out)
{
    const int warp = (blockIdx.x * blockDim.x + threadIdx.x) >> 5;
    const int lane = threadIdx.x & 31;
    if (warp >= NROWS) return;

    const int b = warp / L;
    const size_t nodebase = (size_t)b * L;
    const int is64 = g_adj_is64;

    int   idx = 0;
    float e   = -INFINITY;
    if (lane < D) {
        const size_t ei = (size_t)warp * D + lane;
        int raw = is64 ? adj32[2 * ei] : adj32[ei];   // int64: little-endian low word
        raw = raw < 0 ? 0 : (raw >= L ? L - 1 : raw); // defensive clamp
        idx = raw;
        e   = g_s1[nodebase + idx];
    }
    const int idx0 = __shfl_sync(0xffffffffu, idx, 0);
    const float s2v = g_s2[nodebase + idx0];
    if (lane < D) {
        e += s2v;
        e = (e >= 0.f) ? e : LRELU_ALPHA * e;
    }

    float m = e;
    #pragma unroll
    for (int o = 16; o > 0; o >>= 1) m = fmaxf(m, __shfl_xor_sync(0xffffffffu, m, o));
    float p = (lane < D) ? __expf(e - m) : 0.f;
    float s = p;
    #pragma unroll
    for (int o = 16; o > 0; o >>= 1) s += __shfl_xor_sync(0xffffffffu, s, o);
    const float attn = p / s;

    const __half* yb = g_yh + nodebase * F;
    float4 acc = make_float4(0.f, 0.f, 0.f, 0.f);
    #pragma unroll
    for (int d = 0; d < D; d++) {
        const int   id = __shfl_sync(0xffffffffu, idx,  d);
        const float wt = __shfl_sync(0xffffffffu, attn, d);
        uint2 raw = *(const uint2*)(yb + (size_t)id * F + 4 * lane);
        __half2 h01 = *reinterpret_cast<__half2*>(&raw.x);
        __half2 h23 = *reinterpret_cast<__half2*>(&raw.y);
        float2 f01 = __half22float2(h01);
        float2 f23 = __half22float2(h23);
        acc.x += wt * f01.x; acc.y += wt * f01.y;
        acc.z += wt * f23.x; acc.w += wt * f23.y;
    }

    // elu (alpha=1), fast path
    acc.x = acc.x > 0.f ? acc.x : (__expf(acc.x) - 1.f);
    acc.y = acc.y > 0.f ? acc.y : (__expf(acc.y) - 1.f);
    acc.z = acc.z > 0.f ? acc.z : (__expf(acc.z) - 1.f);
    acc.w = acc.w > 0.f ? acc.w : (__expf(acc.w) - 1.f);

    *(float4*)(out + (size_t)warp * F + 4 * lane) = acc;
}

// ---------------------------------------------------------------------------
extern "C" void kernel_launch(void* const* d_in, const int* in_sizes, int n_in,
                              void* d_out, int out_size)
{
    //   x: 10,240,000 f32 | adj: 1,280,000 (i32 or i64) | W: 16,384 f32 | a: 256 f32
    const float* x   = nullptr;
    const int*   adj = nullptr;
    const float* W   = nullptr;
    const float* a   = nullptr;
    for (int i = 0; i < n_in; i++) {
        switch (in_sizes[i]) {
            case NROWS * F: x   = (const float*)d_in[i]; break;
            case NROWS * D: adj = (const int*)d_in[i];   break;
            case F * F:     W   = (const float*)d_in[i]; break;
            case 2 * F:     a   = (const float*)d_in[i]; break;
            default: break;
        }
    }
    float* out = (float*)d_out;

    prep_kernel<<<1, 256>>>(adj, W);
    gemm_scores_kernel<<<NROWS / 64, 128>>>(x, a);
    attn_out_kernel<<<(NROWS * 32) / 256, 256>>>(adj, out);
}

// round 6
// speedup vs baseline: 1.8324x; 1.1606x over previous
#include <cuda_runtime.h>
#include <cuda_fp16.h>
#include <cstdint>
#include <cstddef>

// FixedGraphAttentionLayer: bs=4, L=20000, D=16, Fin=Fout=128
//   y = x @ W per node (linear rewrite), y stored fp16.
//   e[b,l,d] = s1[adj[b,l,d]] + s2[adj[b,l,0]]  (scores from fp32 accumulators)
// k1 = HMMA (mma.sync m16n8k16 f16f16f32) GEMM + fused scores.
// prep (wide grid) = adj dtype detect + W fragment pre-pack.

#define LRELU_ALPHA 0.2f
static constexpr int BS = 4;
static constexpr int L  = 20000;
static constexpr int D  = 16;
static constexpr int F  = 128;
static constexpr int NROWS = BS * L;   // 80000

__device__ __align__(16) __half g_yh[(size_t)NROWS * F];   // 20.5 MB
__device__ float g_s1[NROWS];
__device__ float g_s2[NROWS];
__device__ int   g_adj_is64;
__device__ __align__(16) uint2 g_Bpack[8 * 16 * 32];       // [kc][nt][lane], 32 KB

// ---------------------------------------------------------------------------
// Prep (16 blocks x 256 threads; one fragment element per thread, one pass):
// adj dtype detect (int64 iff odd 32-bit words all zero; values < 2^31)
// + pack W (fp32 [k=128][n=128]) into mma.m16n8k16 B fragments (fp16).
//   b0 = {W[k0][n], W[k0+1][n]}, b1 = {W[k0+8][n], W[k0+9][n]},
//   k0 = 16*kc + tg*2, n = 8*nt + g   (g = lane>>2, tg = lane&3)
// ---------------------------------------------------------------------------
__global__ void prep_kernel(const int* __restrict__ adj32,
                            const float* __restrict__ W)
{
    const int t = threadIdx.x;
    if (blockIdx.x == 0 && t < 32) {
        const int bad = (adj32[2 * t + 1] != 0) | (adj32[2 * t + 65] != 0);
        const unsigned m = __ballot_sync(0xffffffffu, bad);
        if (t == 0) g_adj_is64 = (m == 0u);
    }
    const int e = blockIdx.x * 256 + t;            // 0..4095
    const int kc = e >> 9, nt = (e >> 5) & 15, lane = e & 31;
    const int g = lane >> 2, tg = lane & 3;
    const int n = nt * 8 + g, k0 = kc * 16 + tg * 2;
    __half2 b0 = __floats2half2_rn(W[k0 * F + n],       W[(k0 + 1) * F + n]);
    __half2 b1 = __floats2half2_rn(W[(k0 + 8) * F + n], W[(k0 + 9) * F + n]);
    uint2 u;
    u.x = *reinterpret_cast<unsigned*>(&b0);
    u.y = *reinterpret_cast<unsigned*>(&b1);
    g_Bpack[e] = u;
}

// ---------------------------------------------------------------------------
// Kernel 1: y = x @ W via HMMA + fused scores. 128 threads, 64 rows/block.
// Warp w owns rows w*16..w*16+15, all 128 cols (16 n-tiles x 8 k-chunks).
// x tile staged fp16 in smem with XOR swizzle (bank-conflict-free frag loads).
// ---------------------------------------------------------------------------
__global__ __launch_bounds__(128)
void gemm_scores_kernel(const float* __restrict__ x,
                        const float* __restrict__ a)
{
    __shared__ __half2 Xs[64 * 64];   // 16 KB: [row][kh2], kh2 swizzled ^(row&7)*4
    __shared__ uint2   Bs[4096];      // 32 KB: [kc][nt][lane]

    const int tid  = threadIdx.x;
    const int lane = tid & 31;
    const int w    = tid >> 5;
    const int g    = lane >> 2;       // 0..7
    const int tg   = lane & 3;        // 0..3
    const int rowbase = blockIdx.x * 64;

    // copy B fragments (32 KB) global -> smem, coalesced
    {
        const uint4* src = (const uint4*)g_Bpack;
        uint4*       dst = (uint4*)Bs;
        #pragma unroll
        for (int i = tid; i < 2048; i += 128) dst[i] = src[i];
    }
    // load x tile (64x128 fp32) -> fp16 swizzled smem
    #pragma unroll
    for (int j = tid; j < 4096; j += 128) {
        const int r = j >> 6, kh2 = j & 63;
        float2 v = *(const float2*)(x + (size_t)(rowbase + r) * F + kh2 * 2);
        Xs[r * 64 + (kh2 ^ ((r & 7) * 4))] = __floats2half2_rn(v.x, v.y);
    }
    __syncthreads();

    // A fragments for this warp's 16 rows, all 8 k-chunks (32 regs)
    unsigned Areg[8][4];
    {
        const int r0 = w * 16 + g, r1 = r0 + 8;
        const int s  = g * 4;
        #pragma unroll
        for (int kc = 0; kc < 8; kc++) {
            const int kl = kc * 8 + tg, kh = kl + 4;
            Areg[kc][0] = *reinterpret_cast<unsigned*>(&Xs[r0 * 64 + (kl ^ s)]);
            Areg[kc][1] = *reinterpret_cast<unsigned*>(&Xs[r1 * 64 + (kl ^ s)]);
            Areg[kc][2] = *reinterpret_cast<unsigned*>(&Xs[r0 * 64 + (kh ^ s)]);
            Areg[kc][3] = *reinterpret_cast<unsigned*>(&Xs[r1 * 64 + (kh ^ s)]);
        }
    }

    float acc[16][4];
    #pragma unroll
    for (int nt = 0; nt < 16; nt++)
        #pragma unroll
        for (int q = 0; q < 4; q++) acc[nt][q] = 0.f;

    #pragma unroll
    for (int nt = 0; nt < 16; nt++) {
        #pragma unroll
        for (int kc = 0; kc < 8; kc++) {
            const uint2 b = Bs[kc * 512 + nt * 32 + lane];
            asm volatile(
                "mma.sync.aligned.m16n8k16.row.col.f32.f16.f16.f32 "
                "{%0,%1,%2,%3}, {%4,%5,%6,%7}, {%8,%9}, {%0,%1,%2,%3};"
                : "+f"(acc[nt][0]), "+f"(acc[nt][1]), "+f"(acc[nt][2]), "+f"(acc[nt][3])
                : "r"(Areg[kc][0]), "r"(Areg[kc][1]), "r"(Areg[kc][2]), "r"(Areg[kc][3]),
                  "r"(b.x), "r"(b.y));
        }
    }

    // scores from fp32 accumulators: rows g (p1a/p2a) and g+8 (p1b/p2b)
    float p1a = 0.f, p1b = 0.f, p2a = 0.f, p2b = 0.f;
    #pragma unroll
    for (int nt = 0; nt < 16; nt++) {
        const float2 a1p = *(const float2*)(a + nt * 8 + tg * 2);
        const float2 a2p = *(const float2*)(a + F + nt * 8 + tg * 2);
        p1a += acc[nt][0] * a1p.x + acc[nt][1] * a1p.y;
        p1b += acc[nt][2] * a1p.x + acc[nt][3] * a1p.y;
        p2a += acc[nt][0] * a2p.x + acc[nt][1] * a2p.y;
        p2b += acc[nt][2] * a2p.x + acc[nt][3] * a2p.y;
    }
    #pragma unroll
    for (int o = 1; o <= 2; o <<= 1) {   // reduce over tg quad (lanes g*4..g*4+3)
        p1a += __shfl_xor_sync(0xffffffffu, p1a, o);
        p1b += __shfl_xor_sync(0xffffffffu, p1b, o);
        p2a += __shfl_xor_sync(0xffffffffu, p2a, o);
        p2b += __shfl_xor_sync(0xffffffffu, p2b, o);
    }
    if (tg == 0) {
        const int r = rowbase + w * 16 + g;
        g_s1[r] = p1a;  g_s2[r] = p2a;
        g_s1[r + 8] = p1b;  g_s2[r + 8] = p2b;
    }

    // stage y (fp16) back into Xs with the same swizzle, then coalesced store
    __syncthreads();
    {
        const int r0 = w * 16 + g;
        const int s  = g * 4;
        #pragma unroll
        for (int nt = 0; nt < 16; nt++) {
            const int c = nt * 4 + tg;
            Xs[r0 * 64 + (c ^ s)]       = __floats2half2_rn(acc[nt][0], acc[nt][1]);
            Xs[(r0 + 8) * 64 + (c ^ s)] = __floats2half2_rn(acc[nt][2], acc[nt][3]);
        }
    }
    __syncthreads();
    {
        const int r = tid >> 1;                 // 2 threads per row
        const int s = (r & 7) * 4;
        const int base = (tid & 1) * 32;        // half2 offset
        __half* dst = g_yh + (size_t)(rowbase + r) * F + base * 2;
        #pragma unroll
        for (int j = 0; j < 8; j++) {
            // (base+j*4) and s both multiples of 4 -> 16B chunk stays contiguous
            uint4 v = *reinterpret_cast<uint4*>(&Xs[r * 64 + ((base + j * 4) ^ s)]);
            *reinterpret_cast<uint4*>(dst + j * 8) = v;
        }
    }
}

// ---------------------------------------------------------------------------
// Kernel 2: one warp per node. softmax(leaky_relu(e)) over D=16, weighted
// fp16 gather (fp32 accumulate), elu. Each lane owns 4 output cols.
// ---------------------------------------------------------------------------
__global__ __launch_bounds__(256)
void attn_out_kernel(const int* __restrict__ adj32,
                     float* __restrict__ out)
{
    const int warp = (blockIdx.x * blockDim.x + threadIdx.x) >> 5;
    const int lane = threadIdx.x & 31;
    if (warp >= NROWS) return;

    const int b = warp / L;
    const size_t nodebase = (size_t)b * L;
    const int is64 = g_adj_is64;

    int   idx = 0;
    float e   = -INFINITY;
    if (lane < D) {
        const size_t ei = (size_t)warp * D + lane;
        int raw;
        if (is64) {
            long long v = ((const long long*)adj32)[ei];   // single LDG.64
            raw = (int)v;
        } else {
            raw = adj32[ei];
        }
        raw = raw < 0 ? 0 : (raw >= L ? L - 1 : raw); // defensive clamp
        idx = raw;
        e   = g_s1[nodebase + idx];
    }
    const int idx0 = __shfl_sync(0xffffffffu, idx, 0);
    const float s2v = g_s2[nodebase + idx0];
    if (lane < D) {
        e += s2v;
        e = (e >= 0.f) ? e : LRELU_ALPHA * e;
    }

    float m = e;
    #pragma unroll
    for (int o = 16; o > 0; o >>= 1) m = fmaxf(m, __shfl_xor_sync(0xffffffffu, m, o));
    float p = (lane < D) ? __expf(e - m) : 0.f;
    float s = p;
    #pragma unroll
    for (int o = 16; o > 0; o >>= 1) s += __shfl_xor_sync(0xffffffffu, s, o);
    const float attn = p / s;

    const __half* yb = g_yh + nodebase * F;
    float4 acc = make_float4(0.f, 0.f, 0.f, 0.f);
    #pragma unroll
    for (int d = 0; d < D; d++) {
        const int   id = __shfl_sync(0xffffffffu, idx,  d);
        const float wt = __shfl_sync(0xffffffffu, attn, d);
        uint2 raw = *(const uint2*)(yb + (size_t)id * F + 4 * lane);
        __half2 h01 = *reinterpret_cast<__half2*>(&raw.x);
        __half2 h23 = *reinterpret_cast<__half2*>(&raw.y);
        float2 f01 = __half22float2(h01);
        float2 f23 = __half22float2(h23);
        acc.x += wt * f01.x; acc.y += wt * f01.y;
        acc.z += wt * f23.x; acc.w += wt * f23.y;
    }

    // elu (alpha=1), fast path
    acc.x = acc.x > 0.f ? acc.x : (__expf(acc.x) - 1.f);
    acc.y = acc.y > 0.f ? acc.y : (__expf(acc.y) - 1.f);
    acc.z = acc.z > 0.f ? acc.z : (__expf(acc.z) - 1.f);
    acc.w = acc.w > 0.f ? acc.w : (__expf(acc.w) - 1.f);

    *(float4*)(out + (size_t)warp * F + 4 * lane) = acc;
}

// ---------------------------------------------------------------------------
extern "C" void kernel_launch(void* const* d_in, const int* in_sizes, int n_in,
                              void* d_out, int out_size)
{
    //   x: 10,240,000 f32 | adj: 1,280,000 (i32 or i64) | W: 16,384 f32 | a: 256 f32
    const float* x   = nullptr;
    const int*   adj = nullptr;
    const float* W   = nullptr;
    const float* a   = nullptr;
    for (int i = 0; i < n_in; i++) {
        switch (in_sizes[i]) {
            case NROWS * F: x   = (const float*)d_in[i]; break;
            case NROWS * D: adj = (const int*)d_in[i];   break;
            case F * F:     W   = (const float*)d_in[i]; break;
            case 2 * F:     a   = (const float*)d_in[i]; break;
            default: break;
        }
    }
    float* out = (float*)d_out;

    prep_kernel<<<16, 256>>>(adj, W);
    gemm_scores_kernel<<<NROWS / 64, 128>>>(x, a);
    attn_out_kernel<<<(NROWS * 32) / 256, 256>>>(adj, out);
}